// round 8
// baseline (speedup 1.0000x reference)
#include <cuda_runtime.h>

#define BB   8
#define DIMM 1024
#define TLEN 4096
#define CBN  4096
#define CDN  8
#define TILE 128

#define OUT_ELEMS (BB*DIMM*TLEN)          /* 33554432 */
#define IDX_OFF   OUT_ELEMS
#define LOSS_OFF  (OUT_ELEMS + BB*TLEN)   /* 33587200 */
#define NTILES    ((BB*TLEN)/TILE)        /* 256 */

// ---------------- scratch (device globals; no allocs allowed) ----------------
__device__ __align__(16) float g_Wt[DIMM*CDN];    // W_in^T [d][o]
__device__ __align__(16) float g_Wb[DIMM*12];     // W_out row (8) + bias + pad(3), 48B/row
__device__ __align__(16) float g_cm[CBN*CDN];     // prescaled codebook: -2*c_n
__device__ __align__(16) float g_csq[CBN];        // ||c_n||^2
__device__ float g_partial[NTILES];

// ---------------- prep: weight-norm + normalized codebook --------------------
__global__ void prep_kernel(const float* __restrict__ v_in,  const float* __restrict__ g_in,
                            const float* __restrict__ cb,
                            const float* __restrict__ v_out, const float* __restrict__ g_out,
                            const float* __restrict__ b_out)
{
    int bid = blockIdx.x, tid = threadIdx.x;

    if (bid < 32) {
        int j = bid * 128 + tid;
        const float4* r = (const float4*)(cb + j * 8);
        float4 a = __ldg(r), b = __ldg(r + 1);
        float v[8] = {a.x, a.y, a.z, a.w, b.x, b.y, b.z, b.w};
        float s = 0.f;
#pragma unroll
        for (int k = 0; k < 8; k++) s = fmaf(v[k], v[k], s);
        float den = fmaxf(__fsqrt_rn(s), 1e-12f);
        float c[8];
#pragma unroll
        for (int k = 0; k < 8; k++) c[k] = __fdiv_rn(v[k], den);
        float cs = 0.f;
#pragma unroll
        for (int k = 0; k < 8; k++) cs = fmaf(c[k], c[k], cs);
        g_csq[j] = cs;
        float4* dst = (float4*)(g_cm + j * 8);          // prescale by -2 (exact)
        dst[0] = make_float4(-2.f*c[0], -2.f*c[1], -2.f*c[2], -2.f*c[3]);
        dst[1] = make_float4(-2.f*c[4], -2.f*c[5], -2.f*c[6], -2.f*c[7]);
    } else if (bid < 40) {
        int o = (bid - 32) * 128 + tid;
        const float4* r = (const float4*)(v_out + o * 8);
        float4 a = __ldg(r), b = __ldg(r + 1);
        float v[8] = {a.x, a.y, a.z, a.w, b.x, b.y, b.z, b.w};
        float s = 0.f;
#pragma unroll
        for (int k = 0; k < 8; k++) s = fmaf(v[k], v[k], s);
        float n = __fsqrt_rn(s);
        float g = __ldg(g_out + o);
        float w[8];
#pragma unroll
        for (int k = 0; k < 8; k++) w[k] = __fdiv_rn(g * v[k], n);
        float4* dst = (float4*)(g_Wb + o * 12);
        dst[0] = make_float4(w[0], w[1], w[2], w[3]);
        dst[1] = make_float4(w[4], w[5], w[6], w[7]);
        dst[2] = make_float4(__ldg(b_out + o), 0.f, 0.f, 0.f);
    } else {
        // W_in: 8 rows, norms over 1024 (identical bits to prior rounds)
        __shared__ float nrm[8];
        int o = tid >> 4, l = tid & 15;
        float s = 0.f;
        for (int d = l; d < DIMM; d += 16) {
            float v = v_in[o * DIMM + d];
            s = fmaf(v, v, s);
        }
#pragma unroll
        for (int off = 8; off >= 1; off >>= 1) s += __shfl_down_sync(0xffffffffu, s, off, 16);
        if (l == 0) nrm[o] = __fsqrt_rn(s);
        __syncthreads();
        for (int e = tid; e < DIMM * CDN; e += 128) {
            int d = e >> 3, oo = e & 7;
            g_Wt[e] = __fdiv_rn(__ldg(g_in + oo) * v_in[oo * DIMM + d], nrm[oo]);
        }
    }
}

// ---------------- fused main: TILE=128 t/block, 4 t per lane, scalar FFMA ----
// smem: [0,36864) partials float4[8w][32lane][9]; reused after reduce:
//       [0,4608) s_q [128t][9]; [4608,9216) s_zs [128t][9];
//       [9216,13312) s_dmin [8w][128t]; [13312,17408) s_imin;
//       [36864,41472) s_ze [128t][9] persistent; [41472,41488) s_lw[4]
__global__ void __launch_bounds__(256, 2)
vq_main_kernel(const float* __restrict__ z, const float* __restrict__ b_in,
               const float* __restrict__ cb, float* __restrict__ out, int write_idx)
{
    __shared__ __align__(16) unsigned char s_raw[41504];
    float* s_ze   = (float*)(s_raw + 36864);
    float* s_lw   = (float*)(s_raw + 41472);
    float* s_q    = (float*)(s_raw);
    float* s_zs   = (float*)(s_raw + 4608);
    float* s_dmin = (float*)(s_raw + 9216);
    int*   s_imin = (int*)  (s_raw + 13312);

    const int tid  = threadIdx.x;
    const int w    = tid >> 5;
    const int lane = tid & 31;
    const int tf0  = blockIdx.x * TILE;    // 128 consecutive t, same b
    const int b    = tf0 >> 12;
    const int t0   = tf0 & (TLEN - 1);

    // ---- phase 1: in_proj partials. warp w covers d in [128w,128w+128) ------
    {
        const float4* zb4 = (const float4*)(z + (size_t)b * DIMM * TLEN + t0) + lane;
        float acc[8][4];
#pragma unroll
        for (int o = 0; o < 8; o++)
#pragma unroll
            for (int t = 0; t < 4; t++) acc[o][t] = 0.f;
        const int d0 = w * 128;
#pragma unroll 4
        for (int i = 0; i < 128; i++) {
            int d = d0 + i;
            float4 zv = __ldcg(zb4 + (size_t)d * (TLEN / 4));
            const float4* wr = (const float4*)(g_Wt + d * 8);
            float4 wA = __ldg(wr), wB = __ldg(wr + 1);
            float wv[8] = {wA.x, wA.y, wA.z, wA.w, wB.x, wB.y, wB.z, wB.w};
#pragma unroll
            for (int o = 0; o < 8; o++) {
                acc[o][0] = fmaf(wv[o], zv.x, acc[o][0]);
                acc[o][1] = fmaf(wv[o], zv.y, acc[o][1]);
                acc[o][2] = fmaf(wv[o], zv.z, acc[o][2]);
                acc[o][3] = fmaf(wv[o], zv.w, acc[o][3]);
            }
        }
        float4* sp = (float4*)(s_raw + ((size_t)(w * 32 + lane) * 9) * 16);
#pragma unroll
        for (int o = 0; o < 8; o++)
            sp[o] = make_float4(acc[o][0], acc[o][1], acc[o][2], acc[o][3]);
    }
    __syncthreads();

    // ---- reduce partials across warps (ascending w, bias last) --------------
    {
        const float* spF = (const float*)s_raw;
#pragma unroll
        for (int j = 0; j < 4; j++) {
            int f = tid + 256 * j;             // 0..1023
            int t = f >> 3, o = f & 7;
            int base = ((t >> 2) * 9 + o) * 4 + (t & 3);
            float s = 0.f;
#pragma unroll
            for (int ww = 0; ww < 8; ww++) s += spF[ww * 32 * 9 * 4 + base];
            s += __ldg(b_in + o);
            s_ze[t * 9 + o] = s;
        }
    }
    __syncthreads();

    // ---- normalize queries (threads 0..127) ---------------------------------
    if (tid < TILE) {
        int t = tid;
        float ze[8];
#pragma unroll
        for (int k = 0; k < 8; k++) ze[k] = s_ze[t * 9 + k];
        float s = 0.f;
#pragma unroll
        for (int k = 0; k < 8; k++) s = fmaf(ze[k], ze[k], s);
        float den = fmaxf(__fsqrt_rn(s), 1e-12f);
        float q[8];
#pragma unroll
        for (int k = 0; k < 8; k++) q[k] = __fdiv_rn(ze[k], den);
#pragma unroll
        for (int k = 0; k < 8; k++) s_q[t * 9 + k] = q[k];
        s_q[t * 9 + 8] = 0.f;   // esq dropped: constant per t, argmin-invariant
    }
    __syncthreads();

    // ---- argmin: warp w scans codes [512w,512w+512); lane owns 4 t ----------
    // score_j = csq_j + sum_k (-2 c_k) q_k   (8 fma per (t,code))
    {
        const int tb = lane * 4;
        float q[4][8];
#pragma unroll
        for (int t = 0; t < 4; t++)
#pragma unroll
            for (int k = 0; k < 8; k++) q[t][k] = s_q[(tb + t) * 9 + k];

        float dmin[4] = {3.402823466e38f, 3.402823466e38f, 3.402823466e38f, 3.402823466e38f};
        int   imin[4] = {0, 0, 0, 0};
        const int j0 = w * 512;
        const float4* crow = (const float4*)g_cm + (size_t)j0 * 2;
        const float2* cq   = (const float2*)g_csq + (j0 >> 1);

        for (int it = 0; it < 256; it++) {
            const float4* cp = crow + it * 4;
            float4 a0 = __ldg(cp),     a1 = __ldg(cp + 1);
            float4 b0 = __ldg(cp + 2), b1 = __ldg(cp + 3);
            float2 cs = __ldg(cq + it);
            const int j = j0 + it * 2;
            float cA[8] = {a0.x, a0.y, a0.z, a0.w, a1.x, a1.y, a1.z, a1.w};
            float cB[8] = {b0.x, b0.y, b0.z, b0.w, b1.x, b1.y, b1.z, b1.w};

#pragma unroll
            for (int t = 0; t < 4; t++) {
                float sA = fmaf(cA[0], q[t][0], cs.x);
                float sB = fmaf(cB[0], q[t][0], cs.y);
#pragma unroll
                for (int k = 1; k < 8; k++) {
                    sA = fmaf(cA[k], q[t][k], sA);
                    sB = fmaf(cB[k], q[t][k], sB);
                }
                if (sA < dmin[t]) { dmin[t] = sA; imin[t] = j; }
                if (sB < dmin[t]) { dmin[t] = sB; imin[t] = j + 1; }
            }
        }
        *(float4*)(s_dmin + w * 128 + tb) = make_float4(dmin[0], dmin[1], dmin[2], dmin[3]);
        *(int4*)  (s_imin + w * 128 + tb) = make_int4(imin[0], imin[1], imin[2], imin[3]);
    }
    __syncthreads();

    // ---- gather/loss/STE (warps 0..3, one t per lane) -----------------------
    if (w < 4) {
        int t = w * 32 + lane;
        float dm = s_dmin[t];
        int   im = s_imin[t];
#pragma unroll
        for (int ww = 1; ww < 8; ww++) {
            float d = s_dmin[ww * 128 + t];
            if (d < dm) { dm = d; im = s_imin[ww * 128 + t]; }
        }
        const float4* cr = (const float4*)(cb + (size_t)im * 8);
        float4 cA = __ldg(cr), cB = __ldg(cr + 1);
        float zq[8] = {cA.x, cA.y, cA.z, cA.w, cB.x, cB.y, cB.z, cB.w};
        float loss = 0.f;
#pragma unroll
        for (int k = 0; k < 8; k++) {
            float zev = s_ze[t * 9 + k];
            float df = zev - zq[k];
            loss = fmaf(df, df, loss);
            s_zs[t * 9 + k] = zev + (zq[k] - zev);     // straight-through value
        }
#pragma unroll
        for (int off = 16; off >= 1; off >>= 1) loss += __shfl_down_sync(0xffffffffu, loss, off);
        if (lane == 0) s_lw[w] = loss;
        if (write_idx) out[IDX_OFF + tf0 + t] = (float)im;
    }
    __syncthreads();

    if (tid == 0)
        g_partial[blockIdx.x] = ((s_lw[0] + s_lw[1]) + s_lw[2]) + s_lw[3];

    // ---- out_proj (fp32 FFMA): warp w covers o in [128w,128w+128) -----------
    {
        const int tb = lane * 4;
        float zs[4][8];
#pragma unroll
        for (int t = 0; t < 4; t++)
#pragma unroll
            for (int k = 0; k < 8; k++) zs[t][k] = s_zs[(tb + t) * 9 + k];

        float* ob = out + (size_t)b * DIMM * TLEN + t0 + tb;
        const int o0 = w * 128;
#pragma unroll 4
        for (int i = 0; i < 128; i++) {
            int o = o0 + i;
            const float4* wr = (const float4*)(g_Wb + o * 12);
            float4 wA = __ldg(wr), wB = __ldg(wr + 1), wC = __ldg(wr + 2);
            float wv[8] = {wA.x, wA.y, wA.z, wA.w, wB.x, wB.y, wB.z, wB.w};
            float r[4];
#pragma unroll
            for (int t = 0; t < 4; t++) {
                float s = 0.f;
#pragma unroll
                for (int k = 0; k < 8; k++) s = fmaf(wv[k], zs[t][k], s);
                r[t] = s + wC.x;                       // bias last, same bits as R5
            }
            __stcg((float4*)(ob + (size_t)o * TLEN), make_float4(r[0], r[1], r[2], r[3]));
        }
    }
}

// ---------------- deterministic loss finalization ----------------------------
__global__ void loss_final_kernel(float* __restrict__ out, int write_loss)
{
    if (!write_loss) return;
    int b = threadIdx.x;
    if (b >= BB) return;
    float s = 0.f;
    for (int i = 0; i < NTILES / BB; i++)
        s += g_partial[b * (NTILES / BB) + i];
    out[LOSS_OFF + b] = s * (1.25f / 32768.0f);
}

// ---------------- launch -----------------------------------------------------
extern "C" void kernel_launch(void* const* d_in, const int* in_sizes, int n_in,
                              void* d_out, int out_size)
{
    const float* z     = (const float*)d_in[0];
    const float* v_in  = (const float*)d_in[1];
    const float* g_in  = (const float*)d_in[2];
    const float* b_in  = (const float*)d_in[3];
    const float* cb    = (const float*)d_in[4];
    const float* v_out = (const float*)d_in[5];
    const float* g_out = (const float*)d_in[6];
    const float* b_out = (const float*)d_in[7];
    float* out = (float*)d_out;

    int write_idx  = (out_size >= IDX_OFF + BB * TLEN) ? 1 : 0;
    int write_loss = (out_size >= LOSS_OFF + BB) ? 1 : 0;

    prep_kernel<<<41, 128>>>(v_in, g_in, cb, v_out, g_out, b_out);
    vq_main_kernel<<<NTILES, 256>>>(z, b_in, cb, out, write_idx);
    loss_final_kernel<<<1, 32>>>(out, write_loss);
}